// round 15
// baseline (speedup 1.0000x reference)
#include <cuda_runtime.h>
#include <cstdint>

#define NNODES 100000
#define MAXE   1000000

// ---------------- scratch (static __device__ globals; no allocation) -------
__device__ __align__(16) float4 g_bufA[NNODES * 32];   // 100000 x 128 floats
__device__ __align__(16) float4 g_bufB[NNODES * 32];   // 100000 x 128 floats
__device__ __align__(16) float4 g_hw3 [NNODES * 10];   // 100000 x 40 floats
__device__ float g_dinv[NNODES];
__device__ int   g_icnt[NNODES];
__device__ int   g_fc  [NNODES];
__device__ int   g_rs  [NNODES + 1];
__device__ int   g_perm[MAXE];
__device__ int   g_bsum[512];
__device__ int   g_boff[512];
__device__ float g_sums[512];
__device__ __align__(16) float g_scale[256];
__device__ __align__(16) float g_shift[256];
__device__ unsigned g_keys[4];

#define SCAN_BLOCKS 391

// ---------------- threefry2x32 (JAX-exact, 20 rounds) ----------------------
__device__ __forceinline__ void tf_round(uint32_t &x0, uint32_t &x1, int r) {
    x0 += x1;
    x1 = __funnelshift_l(x1, x1, r);
    x1 ^= x0;
}

__device__ __forceinline__ uint2 tf_full(uint32_t k0, uint32_t k1, uint32_t x0, uint32_t x1) {
    uint32_t k2 = k0 ^ k1 ^ 0x1BD11BDAu;
    x0 += k0; x1 += k1;
    tf_round(x0,x1,13); tf_round(x0,x1,15); tf_round(x0,x1,26); tf_round(x0,x1,6);
    x0 += k1; x1 += k2 + 1u;
    tf_round(x0,x1,17); tf_round(x0,x1,29); tf_round(x0,x1,16); tf_round(x0,x1,24);
    x0 += k2; x1 += k0 + 2u;
    tf_round(x0,x1,13); tf_round(x0,x1,15); tf_round(x0,x1,26); tf_round(x0,x1,6);
    x0 += k0; x1 += k1 + 3u;
    tf_round(x0,x1,17); tf_round(x0,x1,29); tf_round(x0,x1,16); tf_round(x0,x1,24);
    x0 += k1; x1 += k2 + 4u;
    tf_round(x0,x1,13); tf_round(x0,x1,15); tf_round(x0,x1,26); tf_round(x0,x1,6);
    x0 += k2; x1 += k0 + 5u;
    return make_uint2(x0, x1);
}

__device__ __forceinline__ uint32_t tf_bits_xor(uint32_t k0, uint32_t k1, uint32_t k2, uint32_t ctr) {
    uint32_t x0 = k0;
    uint32_t x1 = ctr + k1;
    tf_round(x0,x1,13); tf_round(x0,x1,15); tf_round(x0,x1,26); tf_round(x0,x1,6);
    x0 += k1; x1 += k2 + 1u;
    tf_round(x0,x1,17); tf_round(x0,x1,29); tf_round(x0,x1,16); tf_round(x0,x1,24);
    x0 += k2; x1 += k0 + 2u;
    tf_round(x0,x1,13); tf_round(x0,x1,15); tf_round(x0,x1,26); tf_round(x0,x1,6);
    x0 += k0; x1 += k1 + 3u;
    tf_round(x0,x1,17); tf_round(x0,x1,29); tf_round(x0,x1,16); tf_round(x0,x1,24);
    x0 += k1; x1 += k2 + 4u;
    tf_round(x0,x1,13); tf_round(x0,x1,15); tf_round(x0,x1,26); tf_round(x0,x1,6);
    x0 += k2; x1 += k0 + 5u;
    return x0 ^ x1;
}

__global__ void k_keys() {
    if (threadIdx.x == 0) {
        uint2 a = tf_full(0u, 42u, 0u, 0u);
        uint2 b = tf_full(0u, 42u, 0u, 1u);
        g_keys[0] = a.x; g_keys[1] = a.y;
        g_keys[2] = b.x; g_keys[3] = b.y;
    }
}

// ---------------- graph preprocessing --------------------------------------
__global__ void k_zero() {
    int i = blockIdx.x * 256 + threadIdx.x;
    if (i < NNODES) { g_icnt[i] = 0; g_fc[i] = 0; }
    if (i < 512)    g_sums[i] = 0.f;
}

__global__ void k_degree(const int* __restrict__ dst, int E) {
    int e = blockIdx.x * 256 + threadIdx.x;
    if (e < E) atomicAdd(&g_icnt[dst[e]], 1);
}

__global__ void k_dinv() {
    int i = blockIdx.x * 256 + threadIdx.x;
    if (i < NNODES) g_dinv[i] = rsqrtf((float)g_icnt[i] + 1.0f);
}

__global__ __launch_bounds__(256) void k_scan_local() {
    __shared__ int s[256];
    int t = threadIdx.x;
    int i = blockIdx.x * 256 + t;
    int v = (i < NNODES) ? g_icnt[i] : 0;
    s[t] = v;
    __syncthreads();
#pragma unroll
    for (int off = 1; off < 256; off <<= 1) {
        int add = (t >= off) ? s[t - off] : 0;
        __syncthreads();
        s[t] += add;
        __syncthreads();
    }
    if (i < NNODES) g_rs[i] = s[t] - v;
    if (t == 255) g_bsum[blockIdx.x] = s[255];
}

__global__ __launch_bounds__(512) void k_scan_block() {
    __shared__ int s[512];
    int t = threadIdx.x;
    int v = (t < SCAN_BLOCKS) ? g_bsum[t] : 0;
    s[t] = v;
    __syncthreads();
#pragma unroll
    for (int off = 1; off < 512; off <<= 1) {
        int add = (t >= off) ? s[t - off] : 0;
        __syncthreads();
        s[t] += add;
        __syncthreads();
    }
    g_boff[t] = s[t] - v;
}

__global__ void k_scan_add(int E) {
    int i = blockIdx.x * 256 + threadIdx.x;
    if (i < NNODES) g_rs[i] += g_boff[blockIdx.x];
    if (i == NNODES) g_rs[NNODES] = E;
}

__global__ void k_fill(const int* __restrict__ src, const int* __restrict__ dst, int E) {
    int e = blockIdx.x * 256 + threadIdx.x;
    if (e >= E) return;
    int d = dst[e];
    int pos = g_rs[d] + atomicAdd(&g_fc[d], 1);
    g_perm[pos] = src[e];
}

// ---------------- bf16 3-term split GEMM (m16n8k16), pair-sync staging -----
// a = ahi + alo (bf16 each); D += ahi*bhi + alo*bhi + ahi*blo (the alo*blo
// term is <= 2^-18|ab| and dropped). fp32 accumulate.
// Block 512 = 16 warps = 8 pairs; pair owns a 32-row A tile (double-buffered,
// pairwise bar.sync). B (hi/lo packed) staged once, block-resident.
// DROP >= 0 fuses BN+ReLU+threefry dropout into A staging.
__device__ __forceinline__ uint2 bf16_split2(float e0, float e1) {
    uint32_t h;
    asm("cvt.rn.bf16x2.f32 %0, %1, %2;" : "=r"(h) : "f"(e1), "f"(e0));
    float r0 = e0 - __uint_as_float(h << 16);
    float r1 = e1 - __uint_as_float(h & 0xFFFF0000u);
    uint32_t l;
    asm("cvt.rn.bf16x2.f32 %0, %1, %2;" : "=r"(l) : "f"(r1), "f"(r0));
    return make_uint2(h, l);
}

#define MMA_BF16(cc, a0,a1,a2,a3, b0,b1)                                       \
    asm volatile("mma.sync.aligned.m16n8k16.row.col.f32.bf16.bf16.f32 "        \
                 "{%0,%1,%2,%3}, {%4,%5,%6,%7}, {%8,%9}, {%0,%1,%2,%3};"       \
                 : "+f"(cc[0]), "+f"(cc[1]), "+f"(cc[2]), "+f"(cc[3])          \
                 : "r"(a0), "r"(a1), "r"(a2), "r"(a3), "r"(b0), "r"(b1))

template<int NCPAD, int DROP>
__global__ __launch_bounds__(512) void sgemm_bf16w(
    const float* __restrict__ A, const float* __restrict__ B,
    float* __restrict__ C, int M, int NC)
{
    constexpr int NT = NCPAD / 16;
    constexpr int BSTR = NCPAD + 2;
    extern __shared__ float4 sm4[];
    float4* Bp = sm4;                          // [8 chunks][4 c][BSTR]
    float4* Ap = sm4 + 8 * 4 * BSTR;           // [8 pairs][2 bufs][4 c][34]

    int tid  = threadIdx.x;
    int warp = tid >> 5, lane = tid & 31;
    int wm = warp >> 1, wn = warp & 1;
    int gid = lane >> 2, ctid = lane & 3;
    int row0 = blockIdx.x * 256;
    int wr = wm * 32;
    int wc = wn * (NCPAD / 2);

    uint32_t kk0 = 0, kk1 = 0, kk2 = 0;
    if (DROP >= 0) {
        kk0 = g_keys[DROP * 2 + 0];
        kk1 = g_keys[DROP * 2 + 1];
        kk2 = kk0 ^ kk1 ^ 0x1BD11BDAu;
    }

    float c[2][NT][4];
#pragma unroll
    for (int mt = 0; mt < 2; mt++)
#pragma unroll
        for (int nt = 0; nt < NT; nt++)
#pragma unroll
            for (int j = 0; j < 4; j++) c[mt][nt][j] = 0.f;

    // ---- stage full B (hi/lo bf16x2 packed), once ----
    for (int idx = tid; idx < 8 * 4 * NCPAD; idx += 512) {
        int cc = idx & (NCPAD - 1);
        int s  = idx / NCPAD;          // 0..31
        int G = s >> 2, cgrp = s & 3;
        int k = G * 16 + cgrp * 2;
        float v0 = (cc < NC) ? B[k * NC + cc]       : 0.f;
        float v1 = (cc < NC) ? B[(k + 1) * NC + cc] : 0.f;
        float v2 = (cc < NC) ? B[(k + 8) * NC + cc] : 0.f;
        float v3 = (cc < NC) ? B[(k + 9) * NC + cc] : 0.f;
        uint2 p0 = bf16_split2(v0, v1);
        uint2 p1 = bf16_split2(v2, v3);
        Bp[(G * 4 + cgrp) * BSTR + cc] =
            make_float4(__uint_as_float(p0.x), __uint_as_float(p1.x),
                        __uint_as_float(p0.y), __uint_as_float(p1.y));
    }

    // ---- A staging ids: 16 rows x 16 k per warp per chunk; 2 lanes/row ----
    int srow = wn * 16 + (lane >> 1);   // local row in pair tile
    int half = lane & 1;                // c-group half
    int gr   = row0 + wr + srow;
    const float* Arow = A + gr * 128 + half * 4;
    float4* ApPair = Ap + wm * 272;     // 2 bufs x 4 x 34

    auto storeA = [&](int buf, int k0c, float4 v0, float4 v1, const uint32_t* msk) {
        float vv[8] = {v0.x, v0.y, v0.z, v0.w, v1.x, v1.y, v1.z, v1.w};
        if (DROP >= 0) {
            int cb = k0c + half * 4;
            float4 s0 = *(const float4*)(g_scale + DROP * 128 + cb);
            float4 s1 = *(const float4*)(g_scale + DROP * 128 + cb + 8);
            float4 t0 = *(const float4*)(g_shift + DROP * 128 + cb);
            float4 t1 = *(const float4*)(g_shift + DROP * 128 + cb + 8);
            float sc[8] = {s0.x, s0.y, s0.z, s0.w, s1.x, s1.y, s1.z, s1.w};
            float sh[8] = {t0.x, t0.y, t0.z, t0.w, t1.x, t1.y, t1.z, t1.w};
#pragma unroll
            for (int t = 0; t < 8; t++) {
                float r = fmaxf(fmaf(vv[t], sc[t], sh[t]), 0.f);
                vv[t] = (msk[t] & 0x80000000u) ? 0.f : r + r;
            }
        }
        uint2 p0 = bf16_split2(vv[0], vv[1]);
        uint2 p1 = bf16_split2(vv[2], vv[3]);
        uint2 p2 = bf16_split2(vv[4], vv[5]);
        uint2 p3 = bf16_split2(vv[6], vv[7]);
        ApPair[buf * 136 + (half * 2 + 0) * 34 + srow] =
            make_float4(__uint_as_float(p0.x), __uint_as_float(p2.x),
                        __uint_as_float(p0.y), __uint_as_float(p2.y));
        ApPair[buf * 136 + (half * 2 + 1) * 34 + srow] =
            make_float4(__uint_as_float(p1.x), __uint_as_float(p3.x),
                        __uint_as_float(p1.y), __uint_as_float(p3.y));
    };

    auto calcMasks = [&](int k0c, uint32_t* msk) {
        uint32_t ibase = (uint32_t)gr * 128u + (uint32_t)(k0c + half * 4);
#pragma unroll
        for (int t = 0; t < 4; t++) {
            msk[t]     = tf_bits_xor(kk0, kk1, kk2, ibase + t);
            msk[t + 4] = tf_bits_xor(kk0, kk1, kk2, ibase + 8 + t);
        }
    };

    // ---- stage chunk 0 -> buf 0 ----
    {
        float4 v0 = make_float4(0.f,0.f,0.f,0.f), v1 = v0;
        if (gr < M) { v0 = *(const float4*)(Arow); v1 = *(const float4*)(Arow + 8); }
        uint32_t msk[8];
        if (DROP >= 0) calcMasks(0, msk);
        storeA(0, 0, v0, v1, msk);
    }
    __syncthreads();   // B + all pairs' chunk0 visible

    for (int it = 0; it < 8; it++) {
        int b = it & 1;
        float4 p0 = make_float4(0.f,0.f,0.f,0.f), p1 = p0;
        uint32_t msk[8];
        if (it < 7 && gr < M) {
            p0 = *(const float4*)(Arow + (it + 1) * 16);
            p1 = *(const float4*)(Arow + (it + 1) * 16 + 8);
        }
        if (DROP >= 0 && it < 7) calcMasks((it + 1) * 16, msk);

        const float4* Ab = ApPair + b * 136 + ctid * 34;
        uint32_t ahi[2][4], alo[2][4];
#pragma unroll
        for (int mt = 0; mt < 2; mt++) {
            float4 A0 = Ab[mt * 16 + gid];
            float4 A1 = Ab[mt * 16 + gid + 8];
            ahi[mt][0] = __float_as_uint(A0.x); ahi[mt][1] = __float_as_uint(A1.x);
            ahi[mt][2] = __float_as_uint(A0.y); ahi[mt][3] = __float_as_uint(A1.y);
            alo[mt][0] = __float_as_uint(A0.z); alo[mt][1] = __float_as_uint(A1.z);
            alo[mt][2] = __float_as_uint(A0.w); alo[mt][3] = __float_as_uint(A1.w);
        }
        const float4* Bbase = Bp + (it * 4 + ctid) * BSTR + wc;
#pragma unroll
        for (int nt = 0; nt < NT; nt++) {
            float4 bb = Bbase[nt * 8 + gid];
            uint32_t bh0 = __float_as_uint(bb.x), bh1 = __float_as_uint(bb.y);
            uint32_t bl0 = __float_as_uint(bb.z), bl1 = __float_as_uint(bb.w);
#pragma unroll
            for (int mt = 0; mt < 2; mt++) {
                MMA_BF16(c[mt][nt], ahi[mt][0], ahi[mt][1], ahi[mt][2], ahi[mt][3], bh0, bh1);
                MMA_BF16(c[mt][nt], alo[mt][0], alo[mt][1], alo[mt][2], alo[mt][3], bh0, bh1);
                MMA_BF16(c[mt][nt], ahi[mt][0], ahi[mt][1], ahi[mt][2], ahi[mt][3], bl0, bl1);
            }
        }
        if (it < 7) {
            storeA(b ^ 1, (it + 1) * 16, p0, p1, msk);
            asm volatile("bar.sync %0, 64;" :: "r"(wm + 1) : "memory");
        }
    }

#pragma unroll
    for (int mt = 0; mt < 2; mt++) {
        int r0 = row0 + wr + mt * 16 + gid;
        int r1 = r0 + 8;
#pragma unroll
        for (int nt = 0; nt < NT; nt++) {
            int ccol = wc + nt * 8 + ctid * 2;
            if (ccol < NC) {
                if (r0 < M) *(float2*)(C + r0 * NC + ccol) = make_float2(c[mt][nt][0], c[mt][nt][1]);
                if (r1 < M) *(float2*)(C + r1 * NC + ccol) = make_float2(c[mt][nt][2], c[mt][nt][3]);
            }
        }
    }
}

// ------ CSR SpMM + contention-free fused BN partial stats ------------------
// Each warp owns a private smem slice (warp's 32 lanes x float4 = all 128
// channels exactly once -> plain STS, no atomics). One syncthreads, then
// 128 threads tree-sum the 8 slices and issue 2 global red.add each.
// NNODES % 8 == 0 so every warp has a valid row (no early exits).
__global__ __launch_bounds__(256) void spmm128s(
    const float4* __restrict__ hw, float4* __restrict__ agg,
    const float* __restrict__ bias, float* __restrict__ sums)
{
    __shared__ float bsum[8][128];
    __shared__ float bsq [8][128];
    int tid = threadIdx.x;
    int w = tid >> 5;
    int row = blockIdx.x * 8 + w;
    int lane = tid & 31;
    int beg = __ldg(&g_rs[row]);
    int end = __ldg(&g_rs[row + 1]);
    float di = g_dinv[row];
    float di2 = di * di;

    float4 self = __ldg(hw + row * 32 + lane);
    float4 b = ((const float4*)bias)[lane];
    float4 acc  = make_float4(fmaf(self.x, di2, b.x), fmaf(self.y, di2, b.y),
                              fmaf(self.z, di2, b.z), fmaf(self.w, di2, b.w));
    float4 acc2 = make_float4(0.f, 0.f, 0.f, 0.f);

    int j = beg;
    for (; j + 1 < end; j += 2) {
        int s0 = __ldg(&g_perm[j]);
        int s1 = __ldg(&g_perm[j + 1]);
        float n0 = __ldg(&g_dinv[s0]) * di;
        float n1 = __ldg(&g_dinv[s1]) * di;
        float4 v0 = __ldg(hw + s0 * 32 + lane);
        float4 v1 = __ldg(hw + s1 * 32 + lane);
        acc.x  = fmaf(v0.x, n0, acc.x);  acc.y  = fmaf(v0.y, n0, acc.y);
        acc.z  = fmaf(v0.z, n0, acc.z);  acc.w  = fmaf(v0.w, n0, acc.w);
        acc2.x = fmaf(v1.x, n1, acc2.x); acc2.y = fmaf(v1.y, n1, acc2.y);
        acc2.z = fmaf(v1.z, n1, acc2.z); acc2.w = fmaf(v1.w, n1, acc2.w);
    }
    if (j < end) {
        int s0 = __ldg(&g_perm[j]);
        float n0 = __ldg(&g_dinv[s0]) * di;
        float4 v0 = __ldg(hw + s0 * 32 + lane);
        acc.x = fmaf(v0.x, n0, acc.x); acc.y = fmaf(v0.y, n0, acc.y);
        acc.z = fmaf(v0.z, n0, acc.z); acc.w = fmaf(v0.w, n0, acc.w);
    }
    float4 o = make_float4(acc.x + acc2.x, acc.y + acc2.y,
                           acc.z + acc2.z, acc.w + acc2.w);
    agg[row * 32 + lane] = o;

    int cch = lane * 4;
    bsum[w][cch + 0] = o.x; bsum[w][cch + 1] = o.y;
    bsum[w][cch + 2] = o.z; bsum[w][cch + 3] = o.w;
    bsq[w][cch + 0] = o.x * o.x; bsq[w][cch + 1] = o.y * o.y;
    bsq[w][cch + 2] = o.z * o.z; bsq[w][cch + 3] = o.w * o.w;
    __syncthreads();
    if (tid < 128) {
        float s = 0.f, q = 0.f;
#pragma unroll
        for (int ww = 0; ww < 8; ww++) {
            s += bsum[ww][tid];
            q += bsq[ww][tid];
        }
        asm volatile("red.global.add.f32 [%0], %1;" :: "l"(sums + tid), "f"(s) : "memory");
        asm volatile("red.global.add.f32 [%0], %1;" :: "l"(sums + 128 + tid), "f"(q) : "memory");
    }
}

// ---------------- fused SpMM(40) + log_softmax -----------------------------
__global__ __launch_bounds__(256) void spmm40ls(
    const float4* __restrict__ hw, float* __restrict__ out,
    const float* __restrict__ bias)
{
    int row = blockIdx.x * 8 + (threadIdx.x >> 5);
    int lane = threadIdx.x & 31;
    bool act = (lane < 10);
    int lc = act ? lane : 9;
    int beg = __ldg(&g_rs[row]);
    int end = __ldg(&g_rs[row + 1]);
    float di = g_dinv[row];
    float di2 = di * di;

    float4 self = __ldg(hw + row * 10 + lc);
    float4 b = ((const float4*)bias)[lc];
    float4 acc = make_float4(fmaf(self.x, di2, b.x), fmaf(self.y, di2, b.y),
                             fmaf(self.z, di2, b.z), fmaf(self.w, di2, b.w));
    for (int j = beg; j < end; j++) {
        int s = __ldg(&g_perm[j]);
        float n = __ldg(&g_dinv[s]) * di;
        float4 v = __ldg(hw + s * 10 + lc);
        acc.x = fmaf(v.x, n, acc.x); acc.y = fmaf(v.y, n, acc.y);
        acc.z = fmaf(v.z, n, acc.z); acc.w = fmaf(v.w, n, acc.w);
    }
    float mx = act ? fmaxf(fmaxf(acc.x, acc.y), fmaxf(acc.z, acc.w)) : -3.4e38f;
#pragma unroll
    for (int o = 16; o; o >>= 1) mx = fmaxf(mx, __shfl_xor_sync(0xffffffffu, mx, o));
    float s = act ? (expf(acc.x - mx) + expf(acc.y - mx) +
                     expf(acc.z - mx) + expf(acc.w - mx)) : 0.f;
#pragma unroll
    for (int o = 16; o; o >>= 1) s += __shfl_xor_sync(0xffffffffu, s, o);
    float l = mx + logf(s);
    if (act)
        ((float4*)out)[row * 10 + lane] =
            make_float4(acc.x - l, acc.y - l, acc.z - l, acc.w - l);
}

// ---------------- BN finalize ----------------------------------------------
__global__ void k_bnfinal(const float* __restrict__ sums,
                          const float* __restrict__ gamma, const float* __restrict__ beta,
                          float* __restrict__ sc, float* __restrict__ sh) {
    int c = threadIdx.x;
    const float inv_n = 1.0f / (float)NNODES;
    float mean = sums[c] * inv_n;
    float var  = sums[128 + c] * inv_n - mean * mean;
    var = fmaxf(var, 0.f);
    float rstd = rsqrtf(var + 1e-5f);
    float a = gamma[c] * rstd;
    sc[c] = a;
    sh[c] = beta[c] - mean * a;
}

// ---------------- launch ---------------------------------------------------
extern "C" void kernel_launch(void* const* d_in, const int* in_sizes, int n_in,
                              void* d_out, int out_size) {
    const float* x   = (const float*)d_in[0];
    const int*   ei  = (const int*)  d_in[1];
    const float* W1  = (const float*)d_in[2];
    const float* b1  = (const float*)d_in[3];
    const float* g1  = (const float*)d_in[4];
    const float* be1 = (const float*)d_in[5];
    const float* W2  = (const float*)d_in[6];
    const float* b2  = (const float*)d_in[7];
    const float* g2  = (const float*)d_in[8];
    const float* be2 = (const float*)d_in[9];
    const float* W3  = (const float*)d_in[10];
    const float* b3  = (const float*)d_in[11];
    int E = in_sizes[1] / 2;
    const int* src = ei;
    const int* dst = ei + E;
    float* out = (float*)d_out;

    void *pA, *pB, *pH3, *pS, *pSc, *pSh;
    cudaGetSymbolAddress(&pA,  g_bufA);
    cudaGetSymbolAddress(&pB,  g_bufB);
    cudaGetSymbolAddress(&pH3, g_hw3);
    cudaGetSymbolAddress(&pS,  g_sums);
    cudaGetSymbolAddress(&pSc, g_scale);
    cudaGetSymbolAddress(&pSh, g_shift);
    float4* bufA = (float4*)pA;
    float4* bufB = (float4*)pB;
    float4* hw3  = (float4*)pH3;
    float* sums  = (float*)pS;
    float* scale = (float*)pSc;
    float* shift = (float*)pSh;

    const int GN     = (NNODES + 255) / 256;
    const int GE     = (E + 255) / 256;
    const int GROW   = NNODES / 8;               // 12500
    const int GM2    = (NNODES + 255) / 256;     // 391

    // smem: B = 8*4*(NCPAD+2) f4; A = 8 pairs * 2 bufs * 4 * 34 f4
    const int SM128 = (8 * 4 * 130 + 8 * 2 * 4 * 34) * (int)sizeof(float4);  // 101376
    const int SM64  = (8 * 4 * 66  + 8 * 2 * 4 * 34) * (int)sizeof(float4);  // 68608
    cudaFuncSetAttribute(sgemm_bf16w<128,-1>, cudaFuncAttributeMaxDynamicSharedMemorySize, SM128);
    cudaFuncSetAttribute(sgemm_bf16w<128, 0>, cudaFuncAttributeMaxDynamicSharedMemorySize, SM128);
    cudaFuncSetAttribute(sgemm_bf16w<64,  1>, cudaFuncAttributeMaxDynamicSharedMemorySize, SM64);

    // preprocessing (layer-1 GEMM kept at launch #4 so ncu captures it)
    k_zero  <<<GN, 256>>>();
    k_degree<<<GE, 256>>>(dst, E);
    k_keys  <<<1, 32>>>();
    sgemm_bf16w<128,-1><<<GM2, 512, SM128>>>(x, W1, (float*)bufA, NNODES, 128);
    k_dinv      <<<GN, 256>>>();
    k_scan_local<<<SCAN_BLOCKS, 256>>>();
    k_scan_block<<<1, 512>>>();
    k_scan_add  <<<SCAN_BLOCKS, 256>>>(E);
    k_fill      <<<GE, 256>>>(src, dst, E);

    // ---- layer 1: spmm (stats fused) -> bnfinal -> (drop fused in GEMM2) --
    spmm128s<<<GROW, 256>>>(bufA, bufB, b1, sums);
    k_bnfinal<<<1, 128>>>(sums, g1, be1, scale, shift);

    // ---- layer 2 ----
    sgemm_bf16w<128, 0><<<GM2, 512, SM128>>>((const float*)bufB, W2, (float*)bufA, NNODES, 128);
    spmm128s<<<GROW, 256>>>(bufA, bufB, b2, sums + 256);
    k_bnfinal<<<1, 128>>>(sums + 256, g2, be2, scale + 128, shift + 128);

    // ---- layer 3 (drop fused) + fused log_softmax ----
    sgemm_bf16w<64, 1><<<GM2, 512, SM64>>>((const float*)bufB, W3, (float*)hw3, NNODES, 40);
    spmm40ls<<<GROW, 256>>>(hw3, out, b3);
}

// round 16
// speedup vs baseline: 1.3097x; 1.3097x over previous
#include <cuda_runtime.h>
#include <cstdint>

#define NNODES 100000
#define MAXE   1000000

// ---------------- scratch (static __device__ globals; no allocation) -------
__device__ __align__(16) float4 g_bufA[NNODES * 32];   // 100000 x 128 floats
__device__ __align__(16) float4 g_bufB[NNODES * 32];   // 100000 x 128 floats
__device__ __align__(16) float4 g_hw3 [NNODES * 10];   // 100000 x 40 floats
__device__ float g_dinv[NNODES];
__device__ int   g_icnt[NNODES];
__device__ int   g_fc  [NNODES];
__device__ int   g_rs  [NNODES + 1];
__device__ int   g_perm[MAXE];
__device__ int   g_bsum[512];
__device__ int   g_boff[512];
__device__ float g_sums[512];
__device__ __align__(16) float g_scale[256];
__device__ __align__(16) float g_shift[256];
__device__ unsigned g_keys[4];

#define SCAN_BLOCKS 391

// ---------------- threefry2x32 (JAX-exact, 20 rounds) ----------------------
__device__ __forceinline__ void tf_round(uint32_t &x0, uint32_t &x1, int r) {
    x0 += x1;
    x1 = __funnelshift_l(x1, x1, r);
    x1 ^= x0;
}

__device__ __forceinline__ uint2 tf_full(uint32_t k0, uint32_t k1, uint32_t x0, uint32_t x1) {
    uint32_t k2 = k0 ^ k1 ^ 0x1BD11BDAu;
    x0 += k0; x1 += k1;
    tf_round(x0,x1,13); tf_round(x0,x1,15); tf_round(x0,x1,26); tf_round(x0,x1,6);
    x0 += k1; x1 += k2 + 1u;
    tf_round(x0,x1,17); tf_round(x0,x1,29); tf_round(x0,x1,16); tf_round(x0,x1,24);
    x0 += k2; x1 += k0 + 2u;
    tf_round(x0,x1,13); tf_round(x0,x1,15); tf_round(x0,x1,26); tf_round(x0,x1,6);
    x0 += k0; x1 += k1 + 3u;
    tf_round(x0,x1,17); tf_round(x0,x1,29); tf_round(x0,x1,16); tf_round(x0,x1,24);
    x0 += k1; x1 += k2 + 4u;
    tf_round(x0,x1,13); tf_round(x0,x1,15); tf_round(x0,x1,26); tf_round(x0,x1,6);
    x0 += k2; x1 += k0 + 5u;
    return make_uint2(x0, x1);
}

__device__ __forceinline__ uint32_t tf_bits_xor(uint32_t k0, uint32_t k1, uint32_t k2, uint32_t ctr) {
    uint32_t x0 = k0;
    uint32_t x1 = ctr + k1;
    tf_round(x0,x1,13); tf_round(x0,x1,15); tf_round(x0,x1,26); tf_round(x0,x1,6);
    x0 += k1; x1 += k2 + 1u;
    tf_round(x0,x1,17); tf_round(x0,x1,29); tf_round(x0,x1,16); tf_round(x0,x1,24);
    x0 += k2; x1 += k0 + 2u;
    tf_round(x0,x1,13); tf_round(x0,x1,15); tf_round(x0,x1,26); tf_round(x0,x1,6);
    x0 += k0; x1 += k1 + 3u;
    tf_round(x0,x1,17); tf_round(x0,x1,29); tf_round(x0,x1,16); tf_round(x0,x1,24);
    x0 += k1; x1 += k2 + 4u;
    tf_round(x0,x1,13); tf_round(x0,x1,15); tf_round(x0,x1,26); tf_round(x0,x1,6);
    x0 += k2; x1 += k0 + 5u;
    return x0 ^ x1;
}

__global__ void k_keys() {
    if (threadIdx.x == 0) {
        uint2 a = tf_full(0u, 42u, 0u, 0u);
        uint2 b = tf_full(0u, 42u, 0u, 1u);
        g_keys[0] = a.x; g_keys[1] = a.y;
        g_keys[2] = b.x; g_keys[3] = b.y;
    }
}

// ---------------- graph preprocessing --------------------------------------
__global__ void k_zero() {
    int i = blockIdx.x * 256 + threadIdx.x;
    if (i < NNODES) { g_icnt[i] = 0; g_fc[i] = 0; }
    if (i < 512)    g_sums[i] = 0.f;
}

__global__ void k_degree(const int* __restrict__ dst, int E) {
    int e = blockIdx.x * 256 + threadIdx.x;
    if (e < E) atomicAdd(&g_icnt[dst[e]], 1);
}

__global__ void k_dinv() {
    int i = blockIdx.x * 256 + threadIdx.x;
    if (i < NNODES) g_dinv[i] = rsqrtf((float)g_icnt[i] + 1.0f);
}

__global__ __launch_bounds__(256) void k_scan_local() {
    __shared__ int s[256];
    int t = threadIdx.x;
    int i = blockIdx.x * 256 + t;
    int v = (i < NNODES) ? g_icnt[i] : 0;
    s[t] = v;
    __syncthreads();
#pragma unroll
    for (int off = 1; off < 256; off <<= 1) {
        int add = (t >= off) ? s[t - off] : 0;
        __syncthreads();
        s[t] += add;
        __syncthreads();
    }
    if (i < NNODES) g_rs[i] = s[t] - v;
    if (t == 255) g_bsum[blockIdx.x] = s[255];
}

__global__ __launch_bounds__(512) void k_scan_block() {
    __shared__ int s[512];
    int t = threadIdx.x;
    int v = (t < SCAN_BLOCKS) ? g_bsum[t] : 0;
    s[t] = v;
    __syncthreads();
#pragma unroll
    for (int off = 1; off < 512; off <<= 1) {
        int add = (t >= off) ? s[t - off] : 0;
        __syncthreads();
        s[t] += add;
        __syncthreads();
    }
    g_boff[t] = s[t] - v;
}

__global__ void k_scan_add(int E) {
    int i = blockIdx.x * 256 + threadIdx.x;
    if (i < NNODES) g_rs[i] += g_boff[blockIdx.x];
    if (i == NNODES) g_rs[NNODES] = E;
}

__global__ void k_fill(const int* __restrict__ src, const int* __restrict__ dst, int E) {
    int e = blockIdx.x * 256 + threadIdx.x;
    if (e >= E) return;
    int d = dst[e];
    int pos = g_rs[d] + atomicAdd(&g_fc[d], 1);
    g_perm[pos] = src[e];
}

// ---------------- bf16 3-term split GEMM (m16n8k16), pair-sync staging -----
// a = ahi + alo (bf16 each); D += ahi*bhi + alo*bhi + ahi*blo (the alo*blo
// term is <= 2^-18|ab| and dropped). fp32 accumulate.
// Block 512 = 16 warps = 8 pairs; pair owns a 32-row A tile (double-buffered,
// pairwise bar.sync). B (hi/lo packed) staged once, block-resident.
// DROP >= 0 fuses BN+ReLU+threefry dropout into A staging.
__device__ __forceinline__ uint2 bf16_split2(float e0, float e1) {
    uint32_t h;
    asm("cvt.rn.bf16x2.f32 %0, %1, %2;" : "=r"(h) : "f"(e1), "f"(e0));
    float r0 = e0 - __uint_as_float(h << 16);
    float r1 = e1 - __uint_as_float(h & 0xFFFF0000u);
    uint32_t l;
    asm("cvt.rn.bf16x2.f32 %0, %1, %2;" : "=r"(l) : "f"(r1), "f"(r0));
    return make_uint2(h, l);
}

#define MMA_BF16(cc, a0,a1,a2,a3, b0,b1)                                       \
    asm volatile("mma.sync.aligned.m16n8k16.row.col.f32.bf16.bf16.f32 "        \
                 "{%0,%1,%2,%3}, {%4,%5,%6,%7}, {%8,%9}, {%0,%1,%2,%3};"       \
                 : "+f"(cc[0]), "+f"(cc[1]), "+f"(cc[2]), "+f"(cc[3])          \
                 : "r"(a0), "r"(a1), "r"(a2), "r"(a3), "r"(b0), "r"(b1))

template<int NCPAD, int DROP>
__global__ __launch_bounds__(512) void sgemm_bf16w(
    const float* __restrict__ A, const float* __restrict__ B,
    float* __restrict__ C, int M, int NC)
{
    constexpr int NT = NCPAD / 16;
    constexpr int BSTR = NCPAD + 2;
    extern __shared__ float4 sm4[];
    float4* Bp = sm4;                          // [8 chunks][4 c][BSTR]
    float4* Ap = sm4 + 8 * 4 * BSTR;           // [8 pairs][2 bufs][4 c][34]

    int tid  = threadIdx.x;
    int warp = tid >> 5, lane = tid & 31;
    int wm = warp >> 1, wn = warp & 1;
    int gid = lane >> 2, ctid = lane & 3;
    int row0 = blockIdx.x * 256;
    int wr = wm * 32;
    int wc = wn * (NCPAD / 2);

    uint32_t kk0 = 0, kk1 = 0, kk2 = 0;
    if (DROP >= 0) {
        kk0 = g_keys[DROP * 2 + 0];
        kk1 = g_keys[DROP * 2 + 1];
        kk2 = kk0 ^ kk1 ^ 0x1BD11BDAu;
    }

    float c[2][NT][4];
#pragma unroll
    for (int mt = 0; mt < 2; mt++)
#pragma unroll
        for (int nt = 0; nt < NT; nt++)
#pragma unroll
            for (int j = 0; j < 4; j++) c[mt][nt][j] = 0.f;

    // ---- stage full B (hi/lo bf16x2 packed), once ----
    for (int idx = tid; idx < 8 * 4 * NCPAD; idx += 512) {
        int cc = idx & (NCPAD - 1);
        int s  = idx / NCPAD;          // 0..31
        int G = s >> 2, cgrp = s & 3;
        int k = G * 16 + cgrp * 2;
        float v0 = (cc < NC) ? B[k * NC + cc]       : 0.f;
        float v1 = (cc < NC) ? B[(k + 1) * NC + cc] : 0.f;
        float v2 = (cc < NC) ? B[(k + 8) * NC + cc] : 0.f;
        float v3 = (cc < NC) ? B[(k + 9) * NC + cc] : 0.f;
        uint2 p0 = bf16_split2(v0, v1);
        uint2 p1 = bf16_split2(v2, v3);
        Bp[(G * 4 + cgrp) * BSTR + cc] =
            make_float4(__uint_as_float(p0.x), __uint_as_float(p1.x),
                        __uint_as_float(p0.y), __uint_as_float(p1.y));
    }

    // ---- A staging ids: 16 rows x 16 k per warp per chunk; 2 lanes/row ----
    int srow = wn * 16 + (lane >> 1);   // local row in pair tile
    int half = lane & 1;                // c-group half
    int gr   = row0 + wr + srow;
    const float* Arow = A + gr * 128 + half * 4;
    float4* ApPair = Ap + wm * 272;     // 2 bufs x 4 x 34

    auto storeA = [&](int buf, int k0c, float4 v0, float4 v1, const uint32_t* msk) {
        float vv[8] = {v0.x, v0.y, v0.z, v0.w, v1.x, v1.y, v1.z, v1.w};
        if (DROP >= 0) {
            int cb = k0c + half * 4;
            float4 s0 = *(const float4*)(g_scale + DROP * 128 + cb);
            float4 s1 = *(const float4*)(g_scale + DROP * 128 + cb + 8);
            float4 t0 = *(const float4*)(g_shift + DROP * 128 + cb);
            float4 t1 = *(const float4*)(g_shift + DROP * 128 + cb + 8);
            float sc[8] = {s0.x, s0.y, s0.z, s0.w, s1.x, s1.y, s1.z, s1.w};
            float sh[8] = {t0.x, t0.y, t0.z, t0.w, t1.x, t1.y, t1.z, t1.w};
#pragma unroll
            for (int t = 0; t < 8; t++) {
                float r = fmaxf(fmaf(vv[t], sc[t], sh[t]), 0.f);
                vv[t] = (msk[t] & 0x80000000u) ? 0.f : r + r;
            }
        }
        uint2 p0 = bf16_split2(vv[0], vv[1]);
        uint2 p1 = bf16_split2(vv[2], vv[3]);
        uint2 p2 = bf16_split2(vv[4], vv[5]);
        uint2 p3 = bf16_split2(vv[6], vv[7]);
        ApPair[buf * 136 + (half * 2 + 0) * 34 + srow] =
            make_float4(__uint_as_float(p0.x), __uint_as_float(p2.x),
                        __uint_as_float(p0.y), __uint_as_float(p2.y));
        ApPair[buf * 136 + (half * 2 + 1) * 34 + srow] =
            make_float4(__uint_as_float(p1.x), __uint_as_float(p3.x),
                        __uint_as_float(p1.y), __uint_as_float(p3.y));
    };

    auto calcMasks = [&](int k0c, uint32_t* msk) {
        uint32_t ibase = (uint32_t)gr * 128u + (uint32_t)(k0c + half * 4);
#pragma unroll
        for (int t = 0; t < 4; t++) {
            msk[t]     = tf_bits_xor(kk0, kk1, kk2, ibase + t);
            msk[t + 4] = tf_bits_xor(kk0, kk1, kk2, ibase + 8 + t);
        }
    };

    // ---- stage chunk 0 -> buf 0 ----
    {
        float4 v0 = make_float4(0.f,0.f,0.f,0.f), v1 = v0;
        if (gr < M) { v0 = *(const float4*)(Arow); v1 = *(const float4*)(Arow + 8); }
        uint32_t msk[8];
        if (DROP >= 0) calcMasks(0, msk);
        storeA(0, 0, v0, v1, msk);
    }
    __syncthreads();   // B + all pairs' chunk0 visible

    for (int it = 0; it < 8; it++) {
        int b = it & 1;
        float4 p0 = make_float4(0.f,0.f,0.f,0.f), p1 = p0;
        uint32_t msk[8];
        if (it < 7 && gr < M) {
            p0 = *(const float4*)(Arow + (it + 1) * 16);
            p1 = *(const float4*)(Arow + (it + 1) * 16 + 8);
        }
        if (DROP >= 0 && it < 7) calcMasks((it + 1) * 16, msk);

        const float4* Ab = ApPair + b * 136 + ctid * 34;
        uint32_t ahi[2][4], alo[2][4];
#pragma unroll
        for (int mt = 0; mt < 2; mt++) {
            float4 A0 = Ab[mt * 16 + gid];
            float4 A1 = Ab[mt * 16 + gid + 8];
            ahi[mt][0] = __float_as_uint(A0.x); ahi[mt][1] = __float_as_uint(A1.x);
            ahi[mt][2] = __float_as_uint(A0.y); ahi[mt][3] = __float_as_uint(A1.y);
            alo[mt][0] = __float_as_uint(A0.z); alo[mt][1] = __float_as_uint(A1.z);
            alo[mt][2] = __float_as_uint(A0.w); alo[mt][3] = __float_as_uint(A1.w);
        }
        const float4* Bbase = Bp + (it * 4 + ctid) * BSTR + wc;
#pragma unroll
        for (int nt = 0; nt < NT; nt++) {
            float4 bb = Bbase[nt * 8 + gid];
            uint32_t bh0 = __float_as_uint(bb.x), bh1 = __float_as_uint(bb.y);
            uint32_t bl0 = __float_as_uint(bb.z), bl1 = __float_as_uint(bb.w);
#pragma unroll
            for (int mt = 0; mt < 2; mt++) {
                MMA_BF16(c[mt][nt], ahi[mt][0], ahi[mt][1], ahi[mt][2], ahi[mt][3], bh0, bh1);
                MMA_BF16(c[mt][nt], alo[mt][0], alo[mt][1], alo[mt][2], alo[mt][3], bh0, bh1);
                MMA_BF16(c[mt][nt], ahi[mt][0], ahi[mt][1], ahi[mt][2], ahi[mt][3], bl0, bl1);
            }
        }
        if (it < 7) {
            storeA(b ^ 1, (it + 1) * 16, p0, p1, msk);
            asm volatile("bar.sync %0, 64;" :: "r"(wm + 1) : "memory");
        }
    }

#pragma unroll
    for (int mt = 0; mt < 2; mt++) {
        int r0 = row0 + wr + mt * 16 + gid;
        int r1 = r0 + 8;
#pragma unroll
        for (int nt = 0; nt < NT; nt++) {
            int ccol = wc + nt * 8 + ctid * 2;
            if (ccol < NC) {
                if (r0 < M) *(float2*)(C + r0 * NC + ccol) = make_float2(c[mt][nt][0], c[mt][nt][1]);
                if (r1 < M) *(float2*)(C + r1 * NC + ccol) = make_float2(c[mt][nt][2], c[mt][nt][3]);
            }
        }
    }
}

// ---------------- CSR SpMM (no atomics, no barriers): ----------------------
__global__ __launch_bounds__(256) void spmm128(
    const float4* __restrict__ hw, float4* __restrict__ agg,
    const float* __restrict__ bias)
{
    int row = blockIdx.x * 8 + (threadIdx.x >> 5);
    if (row >= NNODES) return;
    int lane = threadIdx.x & 31;
    int beg = __ldg(&g_rs[row]);
    int end = __ldg(&g_rs[row + 1]);
    float di = g_dinv[row];
    float di2 = di * di;

    float4 self = __ldg(hw + row * 32 + lane);
    float4 b = ((const float4*)bias)[lane];
    float4 acc  = make_float4(fmaf(self.x, di2, b.x), fmaf(self.y, di2, b.y),
                              fmaf(self.z, di2, b.z), fmaf(self.w, di2, b.w));
    float4 acc2 = make_float4(0.f, 0.f, 0.f, 0.f);

    int j = beg;
    for (; j + 1 < end; j += 2) {
        int s0 = __ldg(&g_perm[j]);
        int s1 = __ldg(&g_perm[j + 1]);
        float n0 = __ldg(&g_dinv[s0]) * di;
        float n1 = __ldg(&g_dinv[s1]) * di;
        float4 v0 = __ldg(hw + s0 * 32 + lane);
        float4 v1 = __ldg(hw + s1 * 32 + lane);
        acc.x  = fmaf(v0.x, n0, acc.x);  acc.y  = fmaf(v0.y, n0, acc.y);
        acc.z  = fmaf(v0.z, n0, acc.z);  acc.w  = fmaf(v0.w, n0, acc.w);
        acc2.x = fmaf(v1.x, n1, acc2.x); acc2.y = fmaf(v1.y, n1, acc2.y);
        acc2.z = fmaf(v1.z, n1, acc2.z); acc2.w = fmaf(v1.w, n1, acc2.w);
    }
    if (j < end) {
        int s0 = __ldg(&g_perm[j]);
        float n0 = __ldg(&g_dinv[s0]) * di;
        float4 v0 = __ldg(hw + s0 * 32 + lane);
        acc.x = fmaf(v0.x, n0, acc.x); acc.y = fmaf(v0.y, n0, acc.y);
        acc.z = fmaf(v0.z, n0, acc.z); acc.w = fmaf(v0.w, n0, acc.w);
    }
    agg[row * 32 + lane] = make_float4(acc.x + acc2.x, acc.y + acc2.y,
                                       acc.z + acc2.z, acc.w + acc2.w);
}

// ---------------- fused SpMM(40) + log_softmax -----------------------------
__global__ __launch_bounds__(256) void spmm40ls(
    const float4* __restrict__ hw, float* __restrict__ out,
    const float* __restrict__ bias)
{
    int row = blockIdx.x * 8 + (threadIdx.x >> 5);
    int lane = threadIdx.x & 31;
    bool act = (lane < 10);
    int lc = act ? lane : 9;
    int beg = __ldg(&g_rs[row]);
    int end = __ldg(&g_rs[row + 1]);
    float di = g_dinv[row];
    float di2 = di * di;

    float4 self = __ldg(hw + row * 10 + lc);
    float4 b = ((const float4*)bias)[lc];
    float4 acc = make_float4(fmaf(self.x, di2, b.x), fmaf(self.y, di2, b.y),
                             fmaf(self.z, di2, b.z), fmaf(self.w, di2, b.w));
    for (int j = beg; j < end; j++) {
        int s = __ldg(&g_perm[j]);
        float n = __ldg(&g_dinv[s]) * di;
        float4 v = __ldg(hw + s * 10 + lc);
        acc.x = fmaf(v.x, n, acc.x); acc.y = fmaf(v.y, n, acc.y);
        acc.z = fmaf(v.z, n, acc.z); acc.w = fmaf(v.w, n, acc.w);
    }
    float mx = act ? fmaxf(fmaxf(acc.x, acc.y), fmaxf(acc.z, acc.w)) : -3.4e38f;
#pragma unroll
    for (int o = 16; o; o >>= 1) mx = fmaxf(mx, __shfl_xor_sync(0xffffffffu, mx, o));
    float s = act ? (expf(acc.x - mx) + expf(acc.y - mx) +
                     expf(acc.z - mx) + expf(acc.w - mx)) : 0.f;
#pragma unroll
    for (int o = 16; o; o >>= 1) s += __shfl_xor_sync(0xffffffffu, s, o);
    float l = mx + logf(s);
    if (act)
        ((float4*)out)[row * 10 + lane] =
            make_float4(acc.x - l, acc.y - l, acc.z - l, acc.w - l);
}

// ---------------- batchnorm stats + finalize -------------------------------
__global__ __launch_bounds__(256) void k_bnstats(const float* __restrict__ h,
                                                 float* __restrict__ sums) {
    __shared__ float ss[256], sq[256];
    int tid = threadIdx.x;
    int c = tid & 127;
    int half = tid >> 7;
    int rbeg = blockIdx.x * 125;        // grid = 800, covers exactly 100000
    float s = 0.f, q = 0.f;
    for (int r = rbeg + half; r < rbeg + 125; r += 2) {
        float v = h[r * 128 + c];
        s += v;
        q = fmaf(v, v, q);
    }
    ss[tid] = s; sq[tid] = q;
    __syncthreads();
    if (half == 0) {
        atomicAdd(&sums[c],       ss[tid] + ss[tid + 128]);
        atomicAdd(&sums[128 + c], sq[tid] + sq[tid + 128]);
    }
}

__global__ void k_bnfinal(const float* __restrict__ sums,
                          const float* __restrict__ gamma, const float* __restrict__ beta,
                          float* __restrict__ sc, float* __restrict__ sh) {
    int c = threadIdx.x;
    const float inv_n = 1.0f / (float)NNODES;
    float mean = sums[c] * inv_n;
    float var  = sums[128 + c] * inv_n - mean * mean;
    var = fmaxf(var, 0.f);
    float rstd = rsqrtf(var + 1e-5f);
    float a = gamma[c] * rstd;
    sc[c] = a;
    sh[c] = beta[c] - mean * a;
}

// ---------------- launch ---------------------------------------------------
extern "C" void kernel_launch(void* const* d_in, const int* in_sizes, int n_in,
                              void* d_out, int out_size) {
    const float* x   = (const float*)d_in[0];
    const int*   ei  = (const int*)  d_in[1];
    const float* W1  = (const float*)d_in[2];
    const float* b1  = (const float*)d_in[3];
    const float* g1  = (const float*)d_in[4];
    const float* be1 = (const float*)d_in[5];
    const float* W2  = (const float*)d_in[6];
    const float* b2  = (const float*)d_in[7];
    const float* g2  = (const float*)d_in[8];
    const float* be2 = (const float*)d_in[9];
    const float* W3  = (const float*)d_in[10];
    const float* b3  = (const float*)d_in[11];
    int E = in_sizes[1] / 2;
    const int* src = ei;
    const int* dst = ei + E;
    float* out = (float*)d_out;

    void *pA, *pB, *pH3, *pS, *pSc, *pSh;
    cudaGetSymbolAddress(&pA,  g_bufA);
    cudaGetSymbolAddress(&pB,  g_bufB);
    cudaGetSymbolAddress(&pH3, g_hw3);
    cudaGetSymbolAddress(&pS,  g_sums);
    cudaGetSymbolAddress(&pSc, g_scale);
    cudaGetSymbolAddress(&pSh, g_shift);
    float4* bufA = (float4*)pA;
    float4* bufB = (float4*)pB;
    float4* hw3  = (float4*)pH3;
    float* sums  = (float*)pS;
    float* scale = (float*)pSc;
    float* shift = (float*)pSh;

    const int GN     = (NNODES + 255) / 256;
    const int GE     = (E + 255) / 256;
    const int GROW   = NNODES / 8;               // 12500
    const int GM2    = (NNODES + 255) / 256;     // 391

    // smem: B = 8*4*(NCPAD+2) f4; A = 8 pairs * 2 bufs * 4 * 34 f4
    const int SM128 = (8 * 4 * 130 + 8 * 2 * 4 * 34) * (int)sizeof(float4);  // 101376
    const int SM64  = (8 * 4 * 66  + 8 * 2 * 4 * 34) * (int)sizeof(float4);  // 68608
    cudaFuncSetAttribute(sgemm_bf16w<128,-1>, cudaFuncAttributeMaxDynamicSharedMemorySize, SM128);
    cudaFuncSetAttribute(sgemm_bf16w<128, 0>, cudaFuncAttributeMaxDynamicSharedMemorySize, SM128);
    cudaFuncSetAttribute(sgemm_bf16w<64,  1>, cudaFuncAttributeMaxDynamicSharedMemorySize, SM64);

    // preprocessing (layer-1 GEMM kept at launch #4 so ncu captures it)
    k_zero  <<<GN, 256>>>();
    k_degree<<<GE, 256>>>(dst, E);
    k_keys  <<<1, 32>>>();
    sgemm_bf16w<128,-1><<<GM2, 512, SM128>>>(x, W1, (float*)bufA, NNODES, 128);
    k_dinv      <<<GN, 256>>>();
    k_scan_local<<<SCAN_BLOCKS, 256>>>();
    k_scan_block<<<1, 512>>>();
    k_scan_add  <<<SCAN_BLOCKS, 256>>>(E);
    k_fill      <<<GE, 256>>>(src, dst, E);

    // ---- layer 1: spmm -> stats -> (BN+ReLU+drop fused into GEMM2) ----
    spmm128 <<<GROW, 256>>>(bufA, bufB, b1);
    k_bnstats<<<800, 256>>>((const float*)bufB, sums);
    k_bnfinal<<<1, 128>>>(sums, g1, be1, scale, shift);

    // ---- layer 2 ----
    sgemm_bf16w<128, 0><<<GM2, 512, SM128>>>((const float*)bufB, W2, (float*)bufA, NNODES, 128);
    spmm128 <<<GROW, 256>>>(bufA, bufB, b2);
    k_bnstats<<<800, 256>>>((const float*)bufB, sums + 256);
    k_bnfinal<<<1, 128>>>(sums + 256, g2, be2, scale + 128, shift + 128);

    // ---- layer 3 (drop fused) + fused log_softmax ----
    sgemm_bf16w<64, 1><<<GM2, 512, SM64>>>((const float*)bufB, W3, (float*)hw3, NNODES, 40);
    spmm40ls<<<GROW, 256>>>(hw3, out, b3);
}

// round 17
// speedup vs baseline: 1.3413x; 1.0241x over previous
#include <cuda_runtime.h>
#include <cstdint>

#define NNODES 100000
#define MAXE   1000000

// ---------------- scratch (static __device__ globals; no allocation) -------
__device__ __align__(16) float4 g_bufA[NNODES * 32];   // 100000 x 128 floats
__device__ __align__(16) float4 g_bufB[NNODES * 32];   // 100000 x 128 floats
__device__ __align__(16) float4 g_hw3 [NNODES * 10];   // 100000 x 40 floats
__device__ float g_dinv[NNODES];
__device__ int   g_icnt[NNODES];
__device__ int   g_fc  [NNODES];
__device__ int   g_rs  [NNODES + 1];
__device__ int   g_perm[MAXE];
__device__ int   g_bsum[512];
__device__ int   g_boff[512];
__device__ float g_sums[512];
__device__ __align__(16) float g_scale[256];
__device__ __align__(16) float g_shift[256];
__device__ unsigned g_keys[4];

#define SCAN_BLOCKS 391

// ---------------- threefry2x32 (JAX-exact, 20 rounds) ----------------------
__device__ __forceinline__ void tf_round(uint32_t &x0, uint32_t &x1, int r) {
    x0 += x1;
    x1 = __funnelshift_l(x1, x1, r);
    x1 ^= x0;
}

__device__ __forceinline__ uint2 tf_full(uint32_t k0, uint32_t k1, uint32_t x0, uint32_t x1) {
    uint32_t k2 = k0 ^ k1 ^ 0x1BD11BDAu;
    x0 += k0; x1 += k1;
    tf_round(x0,x1,13); tf_round(x0,x1,15); tf_round(x0,x1,26); tf_round(x0,x1,6);
    x0 += k1; x1 += k2 + 1u;
    tf_round(x0,x1,17); tf_round(x0,x1,29); tf_round(x0,x1,16); tf_round(x0,x1,24);
    x0 += k2; x1 += k0 + 2u;
    tf_round(x0,x1,13); tf_round(x0,x1,15); tf_round(x0,x1,26); tf_round(x0,x1,6);
    x0 += k0; x1 += k1 + 3u;
    tf_round(x0,x1,17); tf_round(x0,x1,29); tf_round(x0,x1,16); tf_round(x0,x1,24);
    x0 += k1; x1 += k2 + 4u;
    tf_round(x0,x1,13); tf_round(x0,x1,15); tf_round(x0,x1,26); tf_round(x0,x1,6);
    x0 += k2; x1 += k0 + 5u;
    return make_uint2(x0, x1);
}

__device__ __forceinline__ uint32_t tf_bits_xor(uint32_t k0, uint32_t k1, uint32_t k2, uint32_t ctr) {
    uint32_t x0 = k0;
    uint32_t x1 = ctr + k1;
    tf_round(x0,x1,13); tf_round(x0,x1,15); tf_round(x0,x1,26); tf_round(x0,x1,6);
    x0 += k1; x1 += k2 + 1u;
    tf_round(x0,x1,17); tf_round(x0,x1,29); tf_round(x0,x1,16); tf_round(x0,x1,24);
    x0 += k2; x1 += k0 + 2u;
    tf_round(x0,x1,13); tf_round(x0,x1,15); tf_round(x0,x1,26); tf_round(x0,x1,6);
    x0 += k0; x1 += k1 + 3u;
    tf_round(x0,x1,17); tf_round(x0,x1,29); tf_round(x0,x1,16); tf_round(x0,x1,24);
    x0 += k1; x1 += k2 + 4u;
    tf_round(x0,x1,13); tf_round(x0,x1,15); tf_round(x0,x1,26); tf_round(x0,x1,6);
    x0 += k2; x1 += k0 + 5u;
    return x0 ^ x1;
}

__global__ void k_keys() {
    if (threadIdx.x == 0) {
        uint2 a = tf_full(0u, 42u, 0u, 0u);
        uint2 b = tf_full(0u, 42u, 0u, 1u);
        g_keys[0] = a.x; g_keys[1] = a.y;
        g_keys[2] = b.x; g_keys[3] = b.y;
    }
}

// ---------------- graph preprocessing --------------------------------------
__global__ void k_zero() {
    int i = blockIdx.x * 256 + threadIdx.x;
    if (i < NNODES) { g_icnt[i] = 0; g_fc[i] = 0; }
    if (i < 512)    g_sums[i] = 0.f;
}

__global__ void k_degree(const int* __restrict__ dst, int E) {
    int e = blockIdx.x * 256 + threadIdx.x;
    if (e < E) atomicAdd(&g_icnt[dst[e]], 1);
}

__global__ void k_dinv() {
    int i = blockIdx.x * 256 + threadIdx.x;
    if (i < NNODES) g_dinv[i] = rsqrtf((float)g_icnt[i] + 1.0f);
}

__global__ __launch_bounds__(256) void k_scan_local() {
    __shared__ int s[256];
    int t = threadIdx.x;
    int i = blockIdx.x * 256 + t;
    int v = (i < NNODES) ? g_icnt[i] : 0;
    s[t] = v;
    __syncthreads();
#pragma unroll
    for (int off = 1; off < 256; off <<= 1) {
        int add = (t >= off) ? s[t - off] : 0;
        __syncthreads();
        s[t] += add;
        __syncthreads();
    }
    if (i < NNODES) g_rs[i] = s[t] - v;
    if (t == 255) g_bsum[blockIdx.x] = s[255];
}

__global__ __launch_bounds__(512) void k_scan_block() {
    __shared__ int s[512];
    int t = threadIdx.x;
    int v = (t < SCAN_BLOCKS) ? g_bsum[t] : 0;
    s[t] = v;
    __syncthreads();
#pragma unroll
    for (int off = 1; off < 512; off <<= 1) {
        int add = (t >= off) ? s[t - off] : 0;
        __syncthreads();
        s[t] += add;
        __syncthreads();
    }
    g_boff[t] = s[t] - v;
}

__global__ void k_scan_add(int E) {
    int i = blockIdx.x * 256 + threadIdx.x;
    if (i < NNODES) g_rs[i] += g_boff[blockIdx.x];
    if (i == NNODES) g_rs[NNODES] = E;
}

__global__ void k_fill(const int* __restrict__ src, const int* __restrict__ dst, int E) {
    int e = blockIdx.x * 256 + threadIdx.x;
    if (e >= E) return;
    int d = dst[e];
    int pos = g_rs[d] + atomicAdd(&g_fc[d], 1);
    g_perm[pos] = src[e];
}

// ---------------- bf16 3-term split GEMM (m16n8k16), pair-sync staging -----
// a = ahi + alo (bf16 each); D += ahi*bhi + alo*bhi + ahi*blo (the alo*blo
// term is <= 2^-18|ab| and dropped). fp32 accumulate.
// Block 512 = 16 warps = 8 pairs; pair owns a 32-row A tile (double-buffered,
// pairwise bar.sync). B (hi/lo packed) staged once, block-resident.
// DROP >= 0 fuses BN+ReLU+threefry dropout into A staging.
__device__ __forceinline__ uint2 bf16_split2(float e0, float e1) {
    uint32_t h;
    asm("cvt.rn.bf16x2.f32 %0, %1, %2;" : "=r"(h) : "f"(e1), "f"(e0));
    float r0 = e0 - __uint_as_float(h << 16);
    float r1 = e1 - __uint_as_float(h & 0xFFFF0000u);
    uint32_t l;
    asm("cvt.rn.bf16x2.f32 %0, %1, %2;" : "=r"(l) : "f"(r1), "f"(r0));
    return make_uint2(h, l);
}

#define MMA_BF16(cc, a0,a1,a2,a3, b0,b1)                                       \
    asm volatile("mma.sync.aligned.m16n8k16.row.col.f32.bf16.bf16.f32 "        \
                 "{%0,%1,%2,%3}, {%4,%5,%6,%7}, {%8,%9}, {%0,%1,%2,%3};"       \
                 : "+f"(cc[0]), "+f"(cc[1]), "+f"(cc[2]), "+f"(cc[3])          \
                 : "r"(a0), "r"(a1), "r"(a2), "r"(a3), "r"(b0), "r"(b1))

template<int NCPAD, int DROP>
__global__ __launch_bounds__(512) void sgemm_bf16w(
    const float* __restrict__ A, const float* __restrict__ B,
    float* __restrict__ C, int M, int NC)
{
    constexpr int NT = NCPAD / 16;
    constexpr int BSTR = NCPAD + 2;
    extern __shared__ float4 sm4[];
    float4* Bp = sm4;                          // [8 chunks][4 c][BSTR]
    float4* Ap = sm4 + 8 * 4 * BSTR;           // [8 pairs][2 bufs][4 c][34]

    int tid  = threadIdx.x;
    int warp = tid >> 5, lane = tid & 31;
    int wm = warp >> 1, wn = warp & 1;
    int gid = lane >> 2, ctid = lane & 3;
    int row0 = blockIdx.x * 256;
    int wr = wm * 32;
    int wc = wn * (NCPAD / 2);

    uint32_t kk0 = 0, kk1 = 0, kk2 = 0;
    if (DROP >= 0) {
        kk0 = g_keys[DROP * 2 + 0];
        kk1 = g_keys[DROP * 2 + 1];
        kk2 = kk0 ^ kk1 ^ 0x1BD11BDAu;
    }

    float c[2][NT][4];
#pragma unroll
    for (int mt = 0; mt < 2; mt++)
#pragma unroll
        for (int nt = 0; nt < NT; nt++)
#pragma unroll
            for (int j = 0; j < 4; j++) c[mt][nt][j] = 0.f;

    // ---- stage full B (hi/lo bf16x2 packed), once ----
    for (int idx = tid; idx < 8 * 4 * NCPAD; idx += 512) {
        int cc = idx & (NCPAD - 1);
        int s  = idx / NCPAD;          // 0..31
        int G = s >> 2, cgrp = s & 3;
        int k = G * 16 + cgrp * 2;
        float v0 = (cc < NC) ? B[k * NC + cc]       : 0.f;
        float v1 = (cc < NC) ? B[(k + 1) * NC + cc] : 0.f;
        float v2 = (cc < NC) ? B[(k + 8) * NC + cc] : 0.f;
        float v3 = (cc < NC) ? B[(k + 9) * NC + cc] : 0.f;
        uint2 p0 = bf16_split2(v0, v1);
        uint2 p1 = bf16_split2(v2, v3);
        Bp[(G * 4 + cgrp) * BSTR + cc] =
            make_float4(__uint_as_float(p0.x), __uint_as_float(p1.x),
                        __uint_as_float(p0.y), __uint_as_float(p1.y));
    }

    // ---- A staging ids: 16 rows x 16 k per warp per chunk; 2 lanes/row ----
    int srow = wn * 16 + (lane >> 1);   // local row in pair tile
    int half = lane & 1;                // c-group half
    int gr   = row0 + wr + srow;
    const float* Arow = A + gr * 128 + half * 4;
    float4* ApPair = Ap + wm * 272;     // 2 bufs x 4 x 34

    auto storeA = [&](int buf, int k0c, float4 v0, float4 v1, const uint32_t* msk) {
        float vv[8] = {v0.x, v0.y, v0.z, v0.w, v1.x, v1.y, v1.z, v1.w};
        if (DROP >= 0) {
            int cb = k0c + half * 4;
            float4 s0 = *(const float4*)(g_scale + DROP * 128 + cb);
            float4 s1 = *(const float4*)(g_scale + DROP * 128 + cb + 8);
            float4 t0 = *(const float4*)(g_shift + DROP * 128 + cb);
            float4 t1 = *(const float4*)(g_shift + DROP * 128 + cb + 8);
            float sc[8] = {s0.x, s0.y, s0.z, s0.w, s1.x, s1.y, s1.z, s1.w};
            float sh[8] = {t0.x, t0.y, t0.z, t0.w, t1.x, t1.y, t1.z, t1.w};
#pragma unroll
            for (int t = 0; t < 8; t++) {
                float r = fmaxf(fmaf(vv[t], sc[t], sh[t]), 0.f);
                vv[t] = (msk[t] & 0x80000000u) ? 0.f : r + r;
            }
        }
        uint2 p0 = bf16_split2(vv[0], vv[1]);
        uint2 p1 = bf16_split2(vv[2], vv[3]);
        uint2 p2 = bf16_split2(vv[4], vv[5]);
        uint2 p3 = bf16_split2(vv[6], vv[7]);
        ApPair[buf * 136 + (half * 2 + 0) * 34 + srow] =
            make_float4(__uint_as_float(p0.x), __uint_as_float(p2.x),
                        __uint_as_float(p0.y), __uint_as_float(p2.y));
        ApPair[buf * 136 + (half * 2 + 1) * 34 + srow] =
            make_float4(__uint_as_float(p1.x), __uint_as_float(p3.x),
                        __uint_as_float(p1.y), __uint_as_float(p3.y));
    };

    auto calcMasks = [&](int k0c, uint32_t* msk) {
        uint32_t ibase = (uint32_t)gr * 128u + (uint32_t)(k0c + half * 4);
#pragma unroll
        for (int t = 0; t < 4; t++) {
            msk[t]     = tf_bits_xor(kk0, kk1, kk2, ibase + t);
            msk[t + 4] = tf_bits_xor(kk0, kk1, kk2, ibase + 8 + t);
        }
    };

    // ---- stage chunk 0 -> buf 0 ----
    {
        float4 v0 = make_float4(0.f,0.f,0.f,0.f), v1 = v0;
        if (gr < M) { v0 = *(const float4*)(Arow); v1 = *(const float4*)(Arow + 8); }
        uint32_t msk[8];
        if (DROP >= 0) calcMasks(0, msk);
        storeA(0, 0, v0, v1, msk);
    }
    __syncthreads();   // B + all pairs' chunk0 visible

    for (int it = 0; it < 8; it++) {
        int b = it & 1;
        float4 p0 = make_float4(0.f,0.f,0.f,0.f), p1 = p0;
        uint32_t msk[8];
        if (it < 7 && gr < M) {
            p0 = *(const float4*)(Arow + (it + 1) * 16);
            p1 = *(const float4*)(Arow + (it + 1) * 16 + 8);
        }
        if (DROP >= 0 && it < 7) calcMasks((it + 1) * 16, msk);

        const float4* Ab = ApPair + b * 136 + ctid * 34;
        uint32_t ahi[2][4], alo[2][4];
#pragma unroll
        for (int mt = 0; mt < 2; mt++) {
            float4 A0 = Ab[mt * 16 + gid];
            float4 A1 = Ab[mt * 16 + gid + 8];
            ahi[mt][0] = __float_as_uint(A0.x); ahi[mt][1] = __float_as_uint(A1.x);
            ahi[mt][2] = __float_as_uint(A0.y); ahi[mt][3] = __float_as_uint(A1.y);
            alo[mt][0] = __float_as_uint(A0.z); alo[mt][1] = __float_as_uint(A1.z);
            alo[mt][2] = __float_as_uint(A0.w); alo[mt][3] = __float_as_uint(A1.w);
        }
        const float4* Bbase = Bp + (it * 4 + ctid) * BSTR + wc;
#pragma unroll
        for (int nt = 0; nt < NT; nt++) {
            float4 bb = Bbase[nt * 8 + gid];
            uint32_t bh0 = __float_as_uint(bb.x), bh1 = __float_as_uint(bb.y);
            uint32_t bl0 = __float_as_uint(bb.z), bl1 = __float_as_uint(bb.w);
#pragma unroll
            for (int mt = 0; mt < 2; mt++) {
                MMA_BF16(c[mt][nt], ahi[mt][0], ahi[mt][1], ahi[mt][2], ahi[mt][3], bh0, bh1);
                MMA_BF16(c[mt][nt], alo[mt][0], alo[mt][1], alo[mt][2], alo[mt][3], bh0, bh1);
                MMA_BF16(c[mt][nt], ahi[mt][0], ahi[mt][1], ahi[mt][2], ahi[mt][3], bl0, bl1);
            }
        }
        if (it < 7) {
            storeA(b ^ 1, (it + 1) * 16, p0, p1, msk);
            asm volatile("bar.sync %0, 64;" :: "r"(wm + 1) : "memory");
        }
    }

#pragma unroll
    for (int mt = 0; mt < 2; mt++) {
        int r0 = row0 + wr + mt * 16 + gid;
        int r1 = r0 + 8;
#pragma unroll
        for (int nt = 0; nt < NT; nt++) {
            int ccol = wc + nt * 8 + ctid * 2;
            if (ccol < NC) {
                if (r0 < M) *(float2*)(C + r0 * NC + ccol) = make_float2(c[mt][nt][0], c[mt][nt][1]);
                if (r1 < M) *(float2*)(C + r1 * NC + ccol) = make_float2(c[mt][nt][2], c[mt][nt][3]);
            }
        }
    }
}

// ---------------- CSR SpMM (no atomics, no barriers) -----------------------
__global__ __launch_bounds__(256) void spmm128(
    const float4* __restrict__ hw, float4* __restrict__ agg,
    const float* __restrict__ bias)
{
    int row = blockIdx.x * 8 + (threadIdx.x >> 5);
    if (row >= NNODES) return;
    int lane = threadIdx.x & 31;
    int beg = __ldg(&g_rs[row]);
    int end = __ldg(&g_rs[row + 1]);
    float di = g_dinv[row];
    float di2 = di * di;

    float4 self = __ldg(hw + row * 32 + lane);
    float4 b = ((const float4*)bias)[lane];
    float4 acc  = make_float4(fmaf(self.x, di2, b.x), fmaf(self.y, di2, b.y),
                              fmaf(self.z, di2, b.z), fmaf(self.w, di2, b.w));
    float4 acc2 = make_float4(0.f, 0.f, 0.f, 0.f);

    int j = beg;
    for (; j + 1 < end; j += 2) {
        int s0 = __ldg(&g_perm[j]);
        int s1 = __ldg(&g_perm[j + 1]);
        float n0 = __ldg(&g_dinv[s0]) * di;
        float n1 = __ldg(&g_dinv[s1]) * di;
        float4 v0 = __ldg(hw + s0 * 32 + lane);
        float4 v1 = __ldg(hw + s1 * 32 + lane);
        acc.x  = fmaf(v0.x, n0, acc.x);  acc.y  = fmaf(v0.y, n0, acc.y);
        acc.z  = fmaf(v0.z, n0, acc.z);  acc.w  = fmaf(v0.w, n0, acc.w);
        acc2.x = fmaf(v1.x, n1, acc2.x); acc2.y = fmaf(v1.y, n1, acc2.y);
        acc2.z = fmaf(v1.z, n1, acc2.z); acc2.w = fmaf(v1.w, n1, acc2.w);
    }
    if (j < end) {
        int s0 = __ldg(&g_perm[j]);
        float n0 = __ldg(&g_dinv[s0]) * di;
        float4 v0 = __ldg(hw + s0 * 32 + lane);
        acc.x = fmaf(v0.x, n0, acc.x); acc.y = fmaf(v0.y, n0, acc.y);
        acc.z = fmaf(v0.z, n0, acc.z); acc.w = fmaf(v0.w, n0, acc.w);
    }
    agg[row * 32 + lane] = make_float4(acc.x + acc2.x, acc.y + acc2.y,
                                       acc.z + acc2.z, acc.w + acc2.w);
}

// ---------------- fused SpMM(40) + log_softmax -----------------------------
__global__ __launch_bounds__(256) void spmm40ls(
    const float4* __restrict__ hw, float* __restrict__ out,
    const float* __restrict__ bias)
{
    int row = blockIdx.x * 8 + (threadIdx.x >> 5);
    int lane = threadIdx.x & 31;
    bool act = (lane < 10);
    int lc = act ? lane : 9;
    int beg = __ldg(&g_rs[row]);
    int end = __ldg(&g_rs[row + 1]);
    float di = g_dinv[row];
    float di2 = di * di;

    float4 self = __ldg(hw + row * 10 + lc);
    float4 b = ((const float4*)bias)[lc];
    float4 acc = make_float4(fmaf(self.x, di2, b.x), fmaf(self.y, di2, b.y),
                             fmaf(self.z, di2, b.z), fmaf(self.w, di2, b.w));
    for (int j = beg; j < end; j++) {
        int s = __ldg(&g_perm[j]);
        float n = __ldg(&g_dinv[s]) * di;
        float4 v = __ldg(hw + s * 10 + lc);
        acc.x = fmaf(v.x, n, acc.x); acc.y = fmaf(v.y, n, acc.y);
        acc.z = fmaf(v.z, n, acc.z); acc.w = fmaf(v.w, n, acc.w);
    }
    float mx = act ? fmaxf(fmaxf(acc.x, acc.y), fmaxf(acc.z, acc.w)) : -3.4e38f;
#pragma unroll
    for (int o = 16; o; o >>= 1) mx = fmaxf(mx, __shfl_xor_sync(0xffffffffu, mx, o));
    float s = act ? (expf(acc.x - mx) + expf(acc.y - mx) +
                     expf(acc.z - mx) + expf(acc.w - mx)) : 0.f;
#pragma unroll
    for (int o = 16; o; o >>= 1) s += __shfl_xor_sync(0xffffffffu, s, o);
    float l = mx + logf(s);
    if (act)
        ((float4*)out)[row * 10 + lane] =
            make_float4(acc.x - l, acc.y - l, acc.z - l, acc.w - l);
}

// ---------------- batchnorm stats + finalize -------------------------------
__global__ __launch_bounds__(256) void k_bnstats(const float* __restrict__ h,
                                                 float* __restrict__ sums) {
    __shared__ float ss[256], sq[256];
    int tid = threadIdx.x;
    int c = tid & 127;
    int half = tid >> 7;
    int rbeg = blockIdx.x * 125;        // grid = 800, covers exactly 100000
    float s = 0.f, q = 0.f;
    for (int r = rbeg + half; r < rbeg + 125; r += 2) {
        float v = h[r * 128 + c];
        s += v;
        q = fmaf(v, v, q);
    }
    ss[tid] = s; sq[tid] = q;
    __syncthreads();
    if (half == 0) {
        atomicAdd(&sums[c],       ss[tid] + ss[tid + 128]);
        atomicAdd(&sums[128 + c], sq[tid] + sq[tid + 128]);
    }
}

__global__ void k_bnfinal(const float* __restrict__ sums,
                          const float* __restrict__ gamma, const float* __restrict__ beta,
                          float* __restrict__ sc, float* __restrict__ sh) {
    int c = threadIdx.x;
    const float inv_n = 1.0f / (float)NNODES;
    float mean = sums[c] * inv_n;
    float var  = sums[128 + c] * inv_n - mean * mean;
    var = fmaxf(var, 0.f);
    float rstd = rsqrtf(var + 1e-5f);
    float a = gamma[c] * rstd;
    sc[c] = a;
    sh[c] = beta[c] - mean * a;
}

// ---------------- launch ---------------------------------------------------
extern "C" void kernel_launch(void* const* d_in, const int* in_sizes, int n_in,
                              void* d_out, int out_size) {
    const float* x   = (const float*)d_in[0];
    const int*   ei  = (const int*)  d_in[1];
    const float* W1  = (const float*)d_in[2];
    const float* b1  = (const float*)d_in[3];
    const float* g1  = (const float*)d_in[4];
    const float* be1 = (const float*)d_in[5];
    const float* W2  = (const float*)d_in[6];
    const float* b2  = (const float*)d_in[7];
    const float* g2  = (const float*)d_in[8];
    const float* be2 = (const float*)d_in[9];
    const float* W3  = (const float*)d_in[10];
    const float* b3  = (const float*)d_in[11];
    int E = in_sizes[1] / 2;
    const int* src = ei;
    const int* dst = ei + E;
    float* out = (float*)d_out;

    void *pA, *pB, *pH3, *pS, *pSc, *pSh;
    cudaGetSymbolAddress(&pA,  g_bufA);
    cudaGetSymbolAddress(&pB,  g_bufB);
    cudaGetSymbolAddress(&pH3, g_hw3);
    cudaGetSymbolAddress(&pS,  g_sums);
    cudaGetSymbolAddress(&pSc, g_scale);
    cudaGetSymbolAddress(&pSh, g_shift);
    float4* bufA = (float4*)pA;
    float4* bufB = (float4*)pB;
    float4* hw3  = (float4*)pH3;
    float* sums  = (float*)pS;
    float* scale = (float*)pSc;
    float* shift = (float*)pSh;

    const int GN     = (NNODES + 255) / 256;
    const int GE     = (E + 255) / 256;
    const int GROW   = NNODES / 8;               // 12500
    const int GM2    = (NNODES + 255) / 256;     // 391

    // smem: B = 8*4*(NCPAD+2) f4; A = 8 pairs * 2 bufs * 4 * 34 f4
    const int SM128 = (8 * 4 * 130 + 8 * 2 * 4 * 34) * (int)sizeof(float4);  // 101376
    const int SM64  = (8 * 4 * 66  + 8 * 2 * 4 * 34) * (int)sizeof(float4);  // 68608
    cudaFuncSetAttribute(sgemm_bf16w<128,-1>, cudaFuncAttributeMaxDynamicSharedMemorySize, SM128);
    cudaFuncSetAttribute(sgemm_bf16w<128, 0>, cudaFuncAttributeMaxDynamicSharedMemorySize, SM128);
    cudaFuncSetAttribute(sgemm_bf16w<64,  1>, cudaFuncAttributeMaxDynamicSharedMemorySize, SM64);

    // lazily created once (first/correctness call, before graph capture);
    // no device-memory allocation involved
    static cudaStream_t s2 = nullptr;
    static cudaEvent_t evFork = nullptr, evJoin = nullptr;
    if (s2 == nullptr) {
        cudaStreamCreateWithFlags(&s2, cudaStreamNonBlocking);
        cudaEventCreateWithFlags(&evFork, cudaEventDisableTiming);
        cudaEventCreateWithFlags(&evJoin, cudaEventDisableTiming);
    }

    // ---- fork: CSR build on s2 runs concurrently with GEMM1 on the main stream
    cudaEventRecord(evFork, 0);
    cudaStreamWaitEvent(s2, evFork, 0);

    k_zero      <<<GN, 256, 0, s2>>>();
    k_degree    <<<GE, 256, 0, s2>>>(dst, E);
    k_dinv      <<<GN, 256, 0, s2>>>();
    k_scan_local<<<SCAN_BLOCKS, 256, 0, s2>>>();
    k_scan_block<<<1, 512, 0, s2>>>();
    k_scan_add  <<<SCAN_BLOCKS, 256, 0, s2>>>(E);
    k_fill      <<<GE, 256, 0, s2>>>(src, dst, E);
    k_keys      <<<1, 32, 0, s2>>>();

    sgemm_bf16w<128,-1><<<GM2, 512, SM128>>>(x, W1, (float*)bufA, NNODES, 128);

    cudaEventRecord(evJoin, s2);
    cudaStreamWaitEvent(0, evJoin, 0);

    // ---- layer 1: spmm -> stats -> (BN+ReLU+drop fused into GEMM2) ----
    spmm128 <<<GROW, 256>>>(bufA, bufB, b1);
    k_bnstats<<<800, 256>>>((const float*)bufB, sums);
    k_bnfinal<<<1, 128>>>(sums, g1, be1, scale, shift);

    // ---- layer 2 ----
    sgemm_bf16w<128, 0><<<GM2, 512, SM128>>>((const float*)bufB, W2, (float*)bufA, NNODES, 128);
    spmm128 <<<GROW, 256>>>(bufA, bufB, b2);
    k_bnstats<<<800, 256>>>((const float*)bufB, sums + 256);
    k_bnfinal<<<1, 128>>>(sums + 256, g2, be2, scale + 128, shift + 128);

    // ---- layer 3 (drop fused) + fused log_softmax ----
    sgemm_bf16w<64, 1><<<GM2, 512, SM64>>>((const float*)bufB, W3, (float*)hw3, NNODES, 40);
    spmm40ls<<<GROW, 256>>>(hw3, out, b3);
}